// round 6
// baseline (speedup 1.0000x reference)
#include <cuda_runtime.h>

#define B_   2048
#define L_   64
#define N_   1024
#define E_   32
#define SE_  16
#define F_   8
#define NSH  56      // E + F + SE
#define NF   59      // NSH + 3
#define S_   20
#define T    256

#define NT   128     // nodes per base tile
#define GB   8       // batches per base block
#define WSTR 132     // padded smem row stride for wT (multiple of 4, avoids write conflicts)

// per-(b,n) node-independent part of the logits (8 MB scratch)
__device__ __align__(256) float g_base[B_ * N_];
// conv_w column 56 (the "out" gate)
__device__ __align__(256) float g_w56[N_];

// base[b,n] = sum_j shared[b,j]*conv_w[n,j] + x_dist[n]*w57 + x_markov[b,n]*w58
//           + conv_b[n] + fc1_b*w56
__global__ __launch_bounds__(T) void base_kernel(
    const float* __restrict__ conv_w,     // [N, NF] natural layout
    const float* __restrict__ x_dist,
    const float* __restrict__ x_features,
    const float* __restrict__ x_markov,
    const int*   __restrict__ stops,
    const int*   __restrict__ x_week,
    const float* __restrict__ stop_emb,
    const float* __restrict__ week_emb,
    const float* __restrict__ conv_b,
    const float* __restrict__ fc1_b)
{
    __shared__ float s_wT[NF * WSTR];   // wT[j][n_local], 59*132*4 = 31.2 KB
    __shared__ float s_sh[GB][NSH];

    const int tid  = threadIdx.x;
    const int nt   = blockIdx.x & 7;          // node tile 0..7
    const int bt   = blockIdx.x >> 3;         // batch tile 0..255
    const int b0   = bt * GB;
    const int n0g  = nt * NT;                 // global node base of tile
    const int lane = tid & 31;
    const int bg   = tid >> 5;                // batch slot 0..7 (== warp id)
    const int nl   = lane * 4;                // local node base for this thread

    // ---- stage conv_w tile (contiguous 128*59 floats) transposed into smem ----
    {
        const float* src = conv_w + (size_t)n0g * NF;
        for (int e = tid; e < NT * NF; e += T) {
            int n = e / NF;
            int j = e - n * NF;
            s_wT[j * WSTR + n] = src[e];
        }
    }

    // ---- shared (node-independent) features for GB batches ----
    for (int idx = tid; idx < GB * NSH; idx += T) {
        int g = idx / NSH;
        int j = idx - g * NSH;
        int b = b0 + g;
        float v;
        if (j < E_) {
            v = week_emb[x_week[b] * E_ + j];
        } else if (j < E_ + F_) {
            v = x_features[b * F_ + (j - E_)];
        } else {
            int c = j - E_ - F_;
            float s = 0.f;
            #pragma unroll
            for (int st = 0; st < S_; ++st)
                s += stop_emb[stops[b * S_ + st] * SE_ + c];
            v = s;
        }
        s_sh[g][j] = v;
    }
    __syncthreads();

    // ---- dot: thread owns 4 nodes x 1 batch ----
    float d0 = 0.f, d1 = 0.f, d2 = 0.f, d3 = 0.f;
    #pragma unroll 8
    for (int j = 0; j < NSH; ++j) {
        float4 wv = *(const float4*)(&s_wT[j * WSTR + nl]);
        float sh = s_sh[bg][j];
        d0 = fmaf(sh, wv.x, d0);
        d1 = fmaf(sh, wv.y, d1);
        d2 = fmaf(sh, wv.z, d2);
        d3 = fmaf(sh, wv.w, d3);
    }

    float4 w56 = *(const float4*)(&s_wT[(NSH + 0) * WSTR + nl]);
    float4 w57 = *(const float4*)(&s_wT[(NSH + 1) * WSTR + nl]);
    float4 w58 = *(const float4*)(&s_wT[(NSH + 2) * WSTR + nl]);
    float4 cb  = *(const float4*)(&conv_b[n0g + nl]);
    float4 xd  = *(const float4*)(&x_dist[n0g + nl]);
    float  fb  = *fc1_b;

    // export w56 for main_kernel (one warp of one batch-tile per node tile)
    if (bt == 0 && bg == 0)
        *(float4*)(&g_w56[n0g + nl]) = w56;

    size_t base = (size_t)(b0 + bg) * N_ + (size_t)(n0g + nl);
    float4 xm = *(const float4*)(&x_markov[base]);
    float4 o;
    o.x = d0 + xm.x * w58.x + xd.x * w57.x + cb.x + fb * w56.x;
    o.y = d1 + xm.y * w58.y + xd.y * w57.y + cb.y + fb * w56.y;
    o.z = d2 + xm.z * w58.z + xd.z * w57.z + cb.z + fb * w56.z;
    o.w = d3 + xm.w * w58.w + xd.w * w57.w + cb.w + fb * w56.w;
    *(float4*)(&g_base[base]) = o;
}

// hot streaming kernel: one block per batch row (unchanged from R5: 82.6us @ 86% DRAM)
__global__ __launch_bounds__(T, 8) void main_kernel(
    const float* __restrict__ x,      // [B, L, N]
    const int*   __restrict__ x_mask, // [B, N]
    const float* __restrict__ fc1_w,  // [L]
    float*       __restrict__ out)    // [B, N]
{
    __shared__ float s_w[L_];
    __shared__ float s_red[8];

    const int tid  = threadIdx.x;
    const int lane = tid & 31;
    const int warp = tid >> 5;
    const int b    = blockIdx.x;

    if (tid < L_) s_w[tid] = fc1_w[tid];
    __syncthreads();

    const float4* xb = (const float4*)(x + (size_t)b * (L_ * N_)) + tid;
    float4 acc = make_float4(0.f, 0.f, 0.f, 0.f);
    #pragma unroll 4
    for (int l = 0; l < L_; ++l) {
        float4 xv = xb[(size_t)l * (N_ / 4)];
        float wl = s_w[l];
        acc.x = fmaf(wl, xv.x, acc.x);
        acc.y = fmaf(wl, xv.y, acc.y);
        acc.z = fmaf(wl, xv.z, acc.z);
        acc.w = fmaf(wl, xv.w, acc.w);
    }

    size_t base = (size_t)b * N_ + (size_t)tid * 4;
    float4 bs  = *(const float4*)(&g_base[base]);
    float4 w56 = *(const float4*)(&g_w56[tid * 4]);

    float lg0 = bs.x + acc.x * w56.x;
    float lg1 = bs.y + acc.y * w56.y;
    float lg2 = bs.z + acc.z * w56.z;
    float lg3 = bs.w + acc.w * w56.w;

    // ---- log_softmax over the 1024 nodes ----
    float m = fmaxf(fmaxf(lg0, lg1), fmaxf(lg2, lg3));
    #pragma unroll
    for (int off = 16; off > 0; off >>= 1)
        m = fmaxf(m, __shfl_xor_sync(0xffffffffu, m, off));
    if (lane == 0) s_red[warp] = m;
    __syncthreads();
    m = s_red[0];
    #pragma unroll
    for (int w = 1; w < 8; ++w) m = fmaxf(m, s_red[w]);
    __syncthreads();

    float s = __expf(lg0 - m) + __expf(lg1 - m) + __expf(lg2 - m) + __expf(lg3 - m);
    #pragma unroll
    for (int off = 16; off > 0; off >>= 1)
        s += __shfl_xor_sync(0xffffffffu, s, off);
    if (lane == 0) s_red[warp] = s;
    __syncthreads();
    s = 0.f;
    #pragma unroll
    for (int w = 0; w < 8; ++w) s += s_red[w];
    float lse = m + logf(s);

    int4 mk = *(const int4*)(&x_mask[base]);
    float4 o;
    o.x = mk.x ? -1e8f : (lg0 - lse);
    o.y = mk.y ? -1e8f : (lg1 - lse);
    o.z = mk.z ? -1e8f : (lg2 - lse);
    o.w = mk.w ? -1e8f : (lg3 - lse);
    *(float4*)(&out[base]) = o;
}

extern "C" void kernel_launch(void* const* d_in, const int* in_sizes, int n_in,
                              void* d_out, int out_size) {
    const float* x          = (const float*)d_in[0];
    const float* x_dist     = (const float*)d_in[1];
    const float* x_features = (const float*)d_in[2];
    const float* x_markov   = (const float*)d_in[3];
    const int*   stops      = (const int*)  d_in[4];
    const int*   x_week     = (const int*)  d_in[5];
    const int*   x_mask     = (const int*)  d_in[6];
    const float* stop_emb   = (const float*)d_in[7];
    const float* week_emb   = (const float*)d_in[8];
    const float* conv_w     = (const float*)d_in[9];
    const float* conv_b     = (const float*)d_in[10];
    const float* fc1_w      = (const float*)d_in[11];
    const float* fc1_b      = (const float*)d_in[12];
    float*       out        = (float*)d_out;

    base_kernel<<<(N_ / NT) * (B_ / GB), T>>>(conv_w, x_dist, x_features, x_markov,
                                              stops, x_week, stop_emb, week_emb,
                                              conv_b, fc1_b);
    main_kernel<<<B_, T>>>(x, x_mask, fc1_w, out);
}

// round 7
// speedup vs baseline: 1.1813x; 1.1813x over previous
#include <cuda_runtime.h>

#define B_   2048
#define L_   64
#define N_   1024
#define E_   32
#define SE_  16
#define F_   8
#define NSH  56      // E + F + SE
#define NF   59      // NSH + 3
#define S_   20
#define T    256
#define GB   4       // batches per base block

// transposed conv weights: g_convT[j][n] = conv_w[n][j]  (236 KB, L2-resident)
__device__ __align__(256) float g_convT[NF * N_];
// gathered node-independent features: g_shared[b][j]  (459 KB)
__device__ __align__(256) float g_shared[B_ * NSH];
// per-(b,n) node-independent part of the logits (8 MB scratch)
__device__ __align__(256) float g_base[B_ * N_];

// one kernel: conv_w transpose (coalesced reads) + shared-feature gather
__global__ __launch_bounds__(T) void prep_kernel(
    const float* __restrict__ conv_w,     // [N, NF]
    const float* __restrict__ x_features, // [B, F]
    const int*   __restrict__ stops,      // [B, S]
    const int*   __restrict__ x_week,     // [B]
    const float* __restrict__ stop_emb,   // [N, SE]
    const float* __restrict__ week_emb)   // [NW, E]
{
    const int t = blockIdx.x * blockDim.x + threadIdx.x;

    // ---- transpose: thread t handles conv_w linear elements 4t..4t+3 ----
    if (t < (NF * N_) / 4) {
        float4 v = *(const float4*)(conv_w + t * 4);
        int e = t * 4;
        float vv[4] = {v.x, v.y, v.z, v.w};
        #pragma unroll
        for (int u = 0; u < 4; ++u) {
            int n = (e + u) / NF;
            int j = (e + u) - n * NF;
            g_convT[j * N_ + n] = vv[u];
        }
    }

    // ---- gather: item t = (b, j) of g_shared ----
    if (t < B_ * NSH) {
        int b = t / NSH;
        int j = t - b * NSH;
        float v;
        if (j < E_) {
            v = week_emb[x_week[b] * E_ + j];
        } else if (j < E_ + F_) {
            v = x_features[b * F_ + (j - E_)];
        } else {
            int c = j - E_ - F_;
            float s = 0.f;
            #pragma unroll
            for (int st = 0; st < S_; ++st)
                s += stop_emb[stops[b * S_ + st] * SE_ + c];
            v = s;
        }
        g_shared[t] = v;
    }
}

// base[b,n] = sum_j shared[b,j]*convT[j,n] + x_dist[n]*w57 + x_markov[b,n]*w58
//           + conv_b[n] + fc1_b*w56
// thread: 4 nodes (float4) x GB batches; block covers all 1024 nodes x GB batches
__global__ __launch_bounds__(T) void base_kernel(
    const float* __restrict__ x_dist,
    const float* __restrict__ x_markov,
    const float* __restrict__ conv_b,
    const float* __restrict__ fc1_b)
{
    __shared__ float s_sh[GB][NSH];

    const int tid = threadIdx.x;
    const int b0  = blockIdx.x * GB;
    const int n0  = tid * 4;

    if (tid < GB * NSH)
        ((float*)s_sh)[tid] = g_shared[b0 * NSH + tid];
    __syncthreads();

    float d[GB][4];
    #pragma unroll
    for (int g = 0; g < GB; ++g)
        d[g][0] = d[g][1] = d[g][2] = d[g][3] = 0.f;

    #pragma unroll 8
    for (int j = 0; j < NSH; ++j) {
        float4 wv = *(const float4*)(&g_convT[j * N_ + n0]);
        #pragma unroll
        for (int g = 0; g < GB; ++g) {
            float sh = s_sh[g][j];
            d[g][0] = fmaf(sh, wv.x, d[g][0]);
            d[g][1] = fmaf(sh, wv.y, d[g][1]);
            d[g][2] = fmaf(sh, wv.z, d[g][2]);
            d[g][3] = fmaf(sh, wv.w, d[g][3]);
        }
    }

    float4 w56 = *(const float4*)(&g_convT[(NSH + 0) * N_ + n0]);
    float4 w57 = *(const float4*)(&g_convT[(NSH + 1) * N_ + n0]);
    float4 w58 = *(const float4*)(&g_convT[(NSH + 2) * N_ + n0]);
    float4 cb  = *(const float4*)(&conv_b[n0]);
    float4 xd  = *(const float4*)(&x_dist[n0]);
    float  fb  = *fc1_b;

    float4 cst;
    cst.x = xd.x * w57.x + cb.x + fb * w56.x;
    cst.y = xd.y * w57.y + cb.y + fb * w56.y;
    cst.z = xd.z * w57.z + cb.z + fb * w56.z;
    cst.w = xd.w * w57.w + cb.w + fb * w56.w;

    #pragma unroll
    for (int g = 0; g < GB; ++g) {
        size_t base = (size_t)(b0 + g) * N_ + (size_t)n0;
        float4 xm = *(const float4*)(&x_markov[base]);
        float4 o;
        o.x = d[g][0] + xm.x * w58.x + cst.x;
        o.y = d[g][1] + xm.y * w58.y + cst.y;
        o.z = d[g][2] + xm.z * w58.z + cst.z;
        o.w = d[g][3] + xm.w * w58.w + cst.w;
        *(float4*)(&g_base[base]) = o;
    }
}

// hot streaming kernel: persistent over 2 batch rows -> single wave (6.9 CTA/SM)
__global__ __launch_bounds__(T, 8) void main_kernel(
    const float* __restrict__ x,      // [B, L, N]
    const int*   __restrict__ x_mask, // [B, N]
    const float* __restrict__ fc1_w,  // [L]
    float*       __restrict__ out)    // [B, N]
{
    __shared__ float s_w[L_];
    __shared__ float s_red[8];

    const int tid  = threadIdx.x;
    const int lane = tid & 31;
    const int warp = tid >> 5;

    if (tid < L_) s_w[tid] = fc1_w[tid];
    __syncthreads();

    #pragma unroll 1
    for (int bb = 0; bb < 2; ++bb) {
        const int b = blockIdx.x * 2 + bb;

        const float4* xb = (const float4*)(x + (size_t)b * (L_ * N_)) + tid;
        float4 acc = make_float4(0.f, 0.f, 0.f, 0.f);
        #pragma unroll 4
        for (int l = 0; l < L_; ++l) {
            float4 xv = xb[(size_t)l * (N_ / 4)];
            float wl = s_w[l];
            acc.x = fmaf(wl, xv.x, acc.x);
            acc.y = fmaf(wl, xv.y, acc.y);
            acc.z = fmaf(wl, xv.z, acc.z);
            acc.w = fmaf(wl, xv.w, acc.w);
        }

        size_t base = (size_t)b * N_ + (size_t)tid * 4;
        float4 bs  = *(const float4*)(&g_base[base]);
        float4 w56 = *(const float4*)(&g_convT[NSH * N_ + tid * 4]);

        float lg0 = bs.x + acc.x * w56.x;
        float lg1 = bs.y + acc.y * w56.y;
        float lg2 = bs.z + acc.z * w56.z;
        float lg3 = bs.w + acc.w * w56.w;

        // ---- log_softmax over the 1024 nodes ----
        float m = fmaxf(fmaxf(lg0, lg1), fmaxf(lg2, lg3));
        #pragma unroll
        for (int off = 16; off > 0; off >>= 1)
            m = fmaxf(m, __shfl_xor_sync(0xffffffffu, m, off));
        if (lane == 0) s_red[warp] = m;
        __syncthreads();
        m = s_red[0];
        #pragma unroll
        for (int w = 1; w < 8; ++w) m = fmaxf(m, s_red[w]);
        __syncthreads();

        float s = __expf(lg0 - m) + __expf(lg1 - m) + __expf(lg2 - m) + __expf(lg3 - m);
        #pragma unroll
        for (int off = 16; off > 0; off >>= 1)
            s += __shfl_xor_sync(0xffffffffu, s, off);
        if (lane == 0) s_red[warp] = s;
        __syncthreads();
        s = 0.f;
        #pragma unroll
        for (int w = 0; w < 8; ++w) s += s_red[w];
        float lse = m + logf(s);

        int4 mk = *(const int4*)(&x_mask[base]);
        float4 o;
        o.x = mk.x ? -1e8f : (lg0 - lse);
        o.y = mk.y ? -1e8f : (lg1 - lse);
        o.z = mk.z ? -1e8f : (lg2 - lse);
        o.w = mk.w ? -1e8f : (lg3 - lse);
        *(float4*)(&out[base]) = o;

        __syncthreads();   // protect s_red before next iteration
    }
}

extern "C" void kernel_launch(void* const* d_in, const int* in_sizes, int n_in,
                              void* d_out, int out_size) {
    const float* x          = (const float*)d_in[0];
    const float* x_dist     = (const float*)d_in[1];
    const float* x_features = (const float*)d_in[2];
    const float* x_markov   = (const float*)d_in[3];
    const int*   stops      = (const int*)  d_in[4];
    const int*   x_week     = (const int*)  d_in[5];
    const int*   x_mask     = (const int*)  d_in[6];
    const float* stop_emb   = (const float*)d_in[7];
    const float* week_emb   = (const float*)d_in[8];
    const float* conv_w     = (const float*)d_in[9];
    const float* conv_b     = (const float*)d_in[10];
    const float* fc1_w      = (const float*)d_in[11];
    const float* fc1_b      = (const float*)d_in[12];
    float*       out        = (float*)d_out;

    prep_kernel<<<512, T>>>(conv_w, x_features, stops, x_week, stop_emb, week_emb);
    base_kernel<<<B_ / GB, T>>>(x_dist, x_markov, conv_b, fc1_b);
    main_kernel<<<B_ / 2, T>>>(x, x_mask, fc1_w, out);
}